// round 10
// baseline (speedup 1.0000x reference)
#include <cuda_runtime.h>
#include <stdint.h>

// Problem constants
#define BSZ 4
#define SEQ 2048
#define HSZ 1024
#define NH  16
#define HD  64
#define MTOT (BSZ*SEQ)   // 8192

// Scratch (device globals — allocation-free)
__device__ float g_q[BSZ*NH*SEQ*HD];     // [b,h,s,d]
__device__ float g_k[BSZ*NH*SEQ*HD];
__device__ float g_v[BSZ*NH*SEQ*HD];
__device__ float g_attn[BSZ*SEQ*HSZ];    // [b,s,hs] assembled

// ---------------------------------------------------------------------------
// helpers
// ---------------------------------------------------------------------------
__device__ __forceinline__ uint32_t f2tf(float x){
    uint32_t r; asm("cvt.rna.tf32.f32 %0, %1;" : "=r"(r) : "f"(x)); return r;
}

// D += A(16x8) @ B(8x8), tf32
__device__ __forceinline__ void mma8(float c[4],
    uint32_t a0, uint32_t a1, uint32_t a2, uint32_t a3,
    uint32_t b0, uint32_t b1)
{
    asm volatile(
      "mma.sync.aligned.m16n8k8.row.col.f32.tf32.tf32.f32 "
      "{%0,%1,%2,%3}, {%4,%5,%6,%7}, {%8,%9}, {%0,%1,%2,%3};\n"
      : "+f"(c[0]), "+f"(c[1]), "+f"(c[2]), "+f"(c[3])
      : "r"(a0), "r"(a1), "r"(a2), "r"(a3), "r"(b0), "r"(b1));
}

// ---------------------------------------------------------------------------
// 3xTF32 NT GEMM: C[m,n] = sum_k A[m,k] * W[n,k]
// M=8192, N=1024, K=1024. Block 128x128, BK=16, 256 threads, 8 warps (2m x 4n),
// warp tile 64x32 = 4 mtiles(16) x 4 ntiles(8).
// ASEL: 0 = Aext, 1 = g_attn. OUTSEL: 0/1/2 -> g_q/g_k/g_v head-major; 3 -> Cext.
// ---------------------------------------------------------------------------
template<int ASEL, int OUTSEL>
__global__ __launch_bounds__(256)
void gemm_tf32(const float* __restrict__ Aext, const float* __restrict__ W,
               float* __restrict__ Cext)
{
    const float* A = (ASEL == 0) ? Aext : g_attn;
    float* C;
    if      (OUTSEL == 0) C = g_q;
    else if (OUTSEL == 1) C = g_k;
    else if (OUTSEL == 2) C = g_v;
    else                  C = Cext;

    // [row][k] layout, pad 20 -> conflict-free fragment loads
    __shared__ uint32_t AsHi[128][20];
    __shared__ uint32_t AsLo[128][20];
    __shared__ uint32_t BsHi[128][20];
    __shared__ uint32_t BsLo[128][20];

    const int tid  = threadIdx.x;
    const int warp = tid >> 5, lane = tid & 31;
    const int g    = lane >> 2, tig = lane & 3;
    const int wm   = (warp >> 2) * 64;   // 0 or 64
    const int wn   = (warp & 3) * 32;    // 0..96
    const int blockM = blockIdx.y * 128;
    const int blockN = blockIdx.x * 128;
    const int arow = tid >> 2;           // 0..63
    const int ac4  = tid & 3;            // 0..3

    float acc[4][4][4];
    #pragma unroll
    for (int mt = 0; mt < 4; mt++)
        #pragma unroll
        for (int nt = 0; nt < 4; nt++)
            #pragma unroll
            for (int r = 0; r < 4; r++) acc[mt][nt][r] = 0.f;

    for (int kt = 0; kt < 1024; kt += 16) {
        // cooperative load + tf32 hi/lo split
        #pragma unroll
        for (int half = 0; half < 2; half++) {
            int r = arow + half * 64;
            float4 av = *(const float4*)(A + (size_t)(blockM + r) * 1024 + kt + ac4 * 4);
            float4 bv = *(const float4*)(W + (size_t)(blockN + r) * 1024 + kt + ac4 * 4);
            float af[4] = {av.x, av.y, av.z, av.w};
            float bf[4] = {bv.x, bv.y, bv.z, bv.w};
            uint32_t ahi[4], alo[4], bhi[4], blo[4];
            #pragma unroll
            for (int j = 0; j < 4; j++) {
                ahi[j] = f2tf(af[j]);
                alo[j] = f2tf(af[j] - __uint_as_float(ahi[j]));
                bhi[j] = f2tf(bf[j]);
                blo[j] = f2tf(bf[j] - __uint_as_float(bhi[j]));
            }
            *(uint4*)&AsHi[r][ac4*4] = make_uint4(ahi[0],ahi[1],ahi[2],ahi[3]);
            *(uint4*)&AsLo[r][ac4*4] = make_uint4(alo[0],alo[1],alo[2],alo[3]);
            *(uint4*)&BsHi[r][ac4*4] = make_uint4(bhi[0],bhi[1],bhi[2],bhi[3]);
            *(uint4*)&BsLo[r][ac4*4] = make_uint4(blo[0],blo[1],blo[2],blo[3]);
        }
        __syncthreads();

        #pragma unroll
        for (int ks = 0; ks < 2; ks++) {
            const int k0 = ks * 8;
            uint32_t bh[4][2], bl[4][2];
            #pragma unroll
            for (int nt = 0; nt < 4; nt++) {
                int nb = wn + nt * 8 + g;
                bh[nt][0] = BsHi[nb][k0 + tig];
                bh[nt][1] = BsHi[nb][k0 + tig + 4];
                bl[nt][0] = BsLo[nb][k0 + tig];
                bl[nt][1] = BsLo[nb][k0 + tig + 4];
            }
            #pragma unroll
            for (int mt = 0; mt < 4; mt++) {
                int mb = wm + mt * 16;
                uint32_t ah0 = AsHi[mb + g    ][k0 + tig];
                uint32_t ah1 = AsHi[mb + g + 8][k0 + tig];
                uint32_t ah2 = AsHi[mb + g    ][k0 + tig + 4];
                uint32_t ah3 = AsHi[mb + g + 8][k0 + tig + 4];
                uint32_t al0 = AsLo[mb + g    ][k0 + tig];
                uint32_t al1 = AsLo[mb + g + 8][k0 + tig];
                uint32_t al2 = AsLo[mb + g    ][k0 + tig + 4];
                uint32_t al3 = AsLo[mb + g + 8][k0 + tig + 4];
                #pragma unroll
                for (int nt = 0; nt < 4; nt++) {
                    mma8(acc[mt][nt], ah0, ah1, ah2, ah3, bh[nt][0], bh[nt][1]);
                    mma8(acc[mt][nt], al0, al1, al2, al3, bh[nt][0], bh[nt][1]);
                    mma8(acc[mt][nt], ah0, ah1, ah2, ah3, bl[nt][0], bl[nt][1]);
                }
            }
        }
        __syncthreads();
    }

    // epilogue
    #pragma unroll
    for (int mt = 0; mt < 4; mt++) {
        #pragma unroll
        for (int nt = 0; nt < 4; nt++) {
            int m = blockM + wm + mt * 16 + g;
            int n = blockN + wn + nt * 8 + 2 * tig;
            float2 v0 = make_float2(acc[mt][nt][0], acc[mt][nt][1]);
            float2 v1 = make_float2(acc[mt][nt][2], acc[mt][nt][3]);
            if (OUTSEL < 3) {
                int b = m >> 11, s = m & (SEQ - 1);
                int h = n >> 6,  d = n & (HD - 1);
                float* dst = C + (((size_t)(b * NH + h) * SEQ + s) * HD + d);
                *(float2*)dst = v0;
                float* dst2 = C + (((size_t)(b * NH + h) * SEQ + (s + 8)) * HD + d);
                *(float2*)dst2 = v1;
            } else {
                *(float2*)(C + (size_t)m * HSZ + n)       = v0;
                *(float2*)(C + (size_t)(m + 8) * HSZ + n) = v1;
            }
        }
    }
}

// ---------------------------------------------------------------------------
// Tensor-core flash attention (tf32, single pass).
// Block: 128 query rows, one (b,h). 8 warps x 16 rows. KV tiles of 64.
// Smem (dynamic): Ks[64][68] tf32, Vs[64][68] tf32, Ps[128][68] (Q stage -> P)
// ---------------------------------------------------------------------------
__global__ __launch_bounds__(256)
void attn_tc(const unsigned char* __restrict__ mask)
{
    extern __shared__ uint32_t dsm[];
    uint32_t (*Ks)[68] = (uint32_t(*)[68])dsm;
    uint32_t (*Vs)[68] = (uint32_t(*)[68])(dsm + 64 * 68);
    uint32_t (*Ps)[68] = (uint32_t(*)[68])(dsm + 2 * 64 * 68);
    float    (*Pf)[68] = (float   (*)[68])(dsm + 2 * 64 * 68);

    const int bh = blockIdx.y;
    const int b  = bh >> 4, h = bh & 15;
    const int m0 = blockIdx.x * 128;
    const int tid = threadIdx.x;
    const int warp = tid >> 5, lane = tid & 31;
    const int g = lane >> 2, tig = lane & 3;
    const int mw = warp * 16;

    const float* qbase = g_q + (size_t)bh * SEQ * HD;
    const float* kbase = g_k + (size_t)bh * SEQ * HD;
    const float* vbase = g_v + (size_t)bh * SEQ * HD;

    // stage Q (fp32) into Pf
    for (int i = tid; i < 128 * 16; i += 256) {
        int r = i >> 4, c4 = i & 15;
        *(float4*)&Pf[r][c4 * 4] = *(const float4*)(qbase + (size_t)(m0 + r) * HD + c4 * 4);
    }
    __syncthreads();

    // Q fragments (pre-scaled by 1/sqrt(64)=0.125, tf32), register-resident
    uint32_t qa[8][4];
    #pragma unroll
    for (int kd = 0; kd < 8; kd++) {
        qa[kd][0] = f2tf(0.125f * Pf[mw + g    ][kd * 8 + tig]);
        qa[kd][1] = f2tf(0.125f * Pf[mw + g + 8][kd * 8 + tig]);
        qa[kd][2] = f2tf(0.125f * Pf[mw + g    ][kd * 8 + tig + 4]);
        qa[kd][3] = f2tf(0.125f * Pf[mw + g + 8][kd * 8 + tig + 4]);
    }

    float O[8][4];
    #pragma unroll
    for (int dt = 0; dt < 8; dt++)
        O[dt][0] = O[dt][1] = O[dt][2] = O[dt][3] = 0.f;
    float m_a = -1e30f, m_b = -1e30f, l_a = 0.f, l_b = 0.f;

    for (int n0 = 0; n0 < SEQ; n0 += 64) {
        __syncthreads();   // prior tile's Ks/Vs reads done
        for (int i = tid; i < 64 * 16; i += 256) {
            int r = i >> 4, c4 = i & 15;
            float4 kv = *(const float4*)(kbase + (size_t)(n0 + r) * HD + c4 * 4);
            float4 vv = *(const float4*)(vbase + (size_t)(n0 + r) * HD + c4 * 4);
            *(uint4*)&Ks[r][c4*4] = make_uint4(f2tf(kv.x), f2tf(kv.y), f2tf(kv.z), f2tf(kv.w));
            *(uint4*)&Vs[r][c4*4] = make_uint4(f2tf(vv.x), f2tf(vv.y), f2tf(vv.z), f2tf(vv.w));
        }
        __syncthreads();

        // S = (Q*scale) @ K^T   (16 x 64 per warp)
        float S[8][4];
        #pragma unroll
        for (int nt = 0; nt < 8; nt++) {
            S[nt][0] = S[nt][1] = S[nt][2] = S[nt][3] = 0.f;
            #pragma unroll
            for (int kd = 0; kd < 8; kd++) {
                uint32_t b0 = Ks[nt * 8 + g][kd * 8 + tig];
                uint32_t b1 = Ks[nt * 8 + g][kd * 8 + tig + 4];
                mma8(S[nt], qa[kd][0], qa[kd][1], qa[kd][2], qa[kd][3], b0, b1);
            }
        }

        // mask
        #pragma unroll
        for (int nt = 0; nt < 8; nt++) {
            int n = n0 + nt * 8 + 2 * tig;
            const unsigned char* mrow = mask + ((size_t)b * SEQ + (m0 + mw + g)) * SEQ + n;
            uchar2 ma = *(const uchar2*)mrow;
            uchar2 mb2 = *(const uchar2*)(mrow + (size_t)8 * SEQ);
            if (ma.x)  S[nt][0] = -1e30f;
            if (ma.y)  S[nt][1] = -1e30f;
            if (mb2.x) S[nt][2] = -1e30f;
            if (mb2.y) S[nt][3] = -1e30f;
        }

        // online softmax (rows g and g+8)
        float rmax_a = -1e30f, rmax_b = -1e30f;
        #pragma unroll
        for (int nt = 0; nt < 8; nt++) {
            rmax_a = fmaxf(rmax_a, fmaxf(S[nt][0], S[nt][1]));
            rmax_b = fmaxf(rmax_b, fmaxf(S[nt][2], S[nt][3]));
        }
        rmax_a = fmaxf(rmax_a, __shfl_xor_sync(0xffffffffu, rmax_a, 1));
        rmax_a = fmaxf(rmax_a, __shfl_xor_sync(0xffffffffu, rmax_a, 2));
        rmax_b = fmaxf(rmax_b, __shfl_xor_sync(0xffffffffu, rmax_b, 1));
        rmax_b = fmaxf(rmax_b, __shfl_xor_sync(0xffffffffu, rmax_b, 2));

        float mna = fmaxf(m_a, rmax_a), mnb = fmaxf(m_b, rmax_b);
        float alpha_a = __expf(m_a - mna), alpha_b = __expf(m_b - mnb);
        m_a = mna; m_b = mnb;

        float rs_a = 0.f, rs_b = 0.f;
        #pragma unroll
        for (int nt = 0; nt < 8; nt++) {
            float p0 = __expf(S[nt][0] - mna);
            float p1 = __expf(S[nt][1] - mna);
            float p2 = __expf(S[nt][2] - mnb);
            float p3 = __expf(S[nt][3] - mnb);
            rs_a += p0 + p1; rs_b += p2 + p3;
            Ps[mw + g    ][nt * 8 + 2 * tig]     = f2tf(p0);
            Ps[mw + g    ][nt * 8 + 2 * tig + 1] = f2tf(p1);
            Ps[mw + g + 8][nt * 8 + 2 * tig]     = f2tf(p2);
            Ps[mw + g + 8][nt * 8 + 2 * tig + 1] = f2tf(p3);
        }
        rs_a += __shfl_xor_sync(0xffffffffu, rs_a, 1);
        rs_a += __shfl_xor_sync(0xffffffffu, rs_a, 2);
        rs_b += __shfl_xor_sync(0xffffffffu, rs_b, 1);
        rs_b += __shfl_xor_sync(0xffffffffu, rs_b, 2);
        l_a = l_a * alpha_a + rs_a;
        l_b = l_b * alpha_b + rs_b;
        #pragma unroll
        for (int dt = 0; dt < 8; dt++) {
            O[dt][0] *= alpha_a; O[dt][1] *= alpha_a;
            O[dt][2] *= alpha_b; O[dt][3] *= alpha_b;
        }
        __syncwarp();

        // O += P @ V
        #pragma unroll
        for (int kk = 0; kk < 8; kk++) {
            uint32_t pa0 = Ps[mw + g    ][kk * 8 + tig];
            uint32_t pa1 = Ps[mw + g + 8][kk * 8 + tig];
            uint32_t pa2 = Ps[mw + g    ][kk * 8 + tig + 4];
            uint32_t pa3 = Ps[mw + g + 8][kk * 8 + tig + 4];
            #pragma unroll
            for (int dt = 0; dt < 8; dt++) {
                uint32_t b0 = Vs[kk * 8 + tig    ][dt * 8 + g];
                uint32_t b1 = Vs[kk * 8 + tig + 4][dt * 8 + g];
                mma8(O[dt], pa0, pa1, pa2, pa3, b0, b1);
            }
        }
    }

    // write normalized output, assembled [b,s,hs]
    float inva = 1.0f / l_a, invb = 1.0f / l_b;
    #pragma unroll
    for (int dt = 0; dt < 8; dt++) {
        int d = h * HD + dt * 8 + 2 * tig;
        float* dst0 = g_attn + ((size_t)(b * SEQ + m0 + mw + g)) * HSZ + d;
        *(float2*)dst0 = make_float2(O[dt][0] * inva, O[dt][1] * inva);
        float* dst1 = g_attn + ((size_t)(b * SEQ + m0 + mw + g + 8)) * HSZ + d;
        *(float2*)dst1 = make_float2(O[dt][2] * invb, O[dt][3] * invb);
    }
}

// ---------------------------------------------------------------------------
extern "C" void kernel_launch(void* const* d_in, const int* in_sizes, int n_in,
                              void* d_out, int out_size)
{
    const float* Q  = (const float*)d_in[0];
    const float* K  = (const float*)d_in[1];
    const float* V  = (const float*)d_in[2];
    const unsigned char* mask = (const unsigned char*)d_in[3];
    const float* Wq = (const float*)d_in[4];
    const float* Wk = (const float*)d_in[5];
    const float* Wv = (const float*)d_in[6];
    const float* Wo = (const float*)d_in[7];
    float* out = (float*)d_out;

    dim3 gGemm(HSZ / 128, MTOT / 128);   // (8, 64)

    gemm_tf32<0,0><<<gGemm, 256>>>(Q, Wq, nullptr);
    gemm_tf32<0,1><<<gGemm, 256>>>(K, Wk, nullptr);
    gemm_tf32<0,2><<<gGemm, 256>>>(V, Wv, nullptr);

    const int attnSmem = (2 * 64 * 68 + 128 * 68) * (int)sizeof(uint32_t);  // 69632
    cudaFuncSetAttribute(attn_tc, cudaFuncAttributeMaxDynamicSharedMemorySize, attnSmem);
    attn_tc<<<dim3(SEQ / 128, BSZ * NH), 256, attnSmem>>>(mask);

    gemm_tf32<1,3><<<gGemm, 256>>>(nullptr, Wo, out);
}

// round 11
// speedup vs baseline: 1.0062x; 1.0062x over previous
#include <cuda_runtime.h>
#include <stdint.h>

// Problem constants
#define BSZ 4
#define SEQ 2048
#define HSZ 1024
#define NH  16
#define HD  64
#define MTOT (BSZ*SEQ)   // 8192

// Scratch (device globals — allocation-free)
__device__ float g_q[BSZ*NH*SEQ*HD];     // [b,h,s,d]
__device__ float g_k[BSZ*NH*SEQ*HD];
__device__ float g_v[BSZ*NH*SEQ*HD];
__device__ float g_attn[BSZ*SEQ*HSZ];    // [b,s,hs] assembled

// ---------------------------------------------------------------------------
// helpers
// ---------------------------------------------------------------------------
__device__ __forceinline__ uint32_t f2tf(float x){
    uint32_t r; asm("cvt.rna.tf32.f32 %0, %1;" : "=r"(r) : "f"(x)); return r;
}

// D += A(16x8) @ B(8x8), tf32
__device__ __forceinline__ void mma8(float c[4],
    uint32_t a0, uint32_t a1, uint32_t a2, uint32_t a3,
    uint32_t b0, uint32_t b1)
{
    asm volatile(
      "mma.sync.aligned.m16n8k8.row.col.f32.tf32.tf32.f32 "
      "{%0,%1,%2,%3}, {%4,%5,%6,%7}, {%8,%9}, {%0,%1,%2,%3};\n"
      : "+f"(c[0]), "+f"(c[1]), "+f"(c[2]), "+f"(c[3])
      : "r"(a0), "r"(a1), "r"(a2), "r"(a3), "r"(b0), "r"(b1));
}

// ---------------------------------------------------------------------------
// 3xTF32 NT GEMM: C[m,n] = sum_k A[m,k] * W[n,k]
// M=8192, N=1024, K=1024. Block 128x128, BK=16, 256 threads, 8 warps (2m x 4n),
// warp tile 64x32 = 4 mtiles(16) x 4 ntiles(8).
// ASEL: 0 = Aext, 1 = g_attn. OUTSEL: 0/1/2 -> g_q/g_k/g_v head-major; 3 -> Cext.
// ---------------------------------------------------------------------------
template<int ASEL, int OUTSEL>
__global__ __launch_bounds__(256)
void gemm_tf32(const float* __restrict__ Aext, const float* __restrict__ W,
               float* __restrict__ Cext)
{
    const float* A = (ASEL == 0) ? Aext : g_attn;
    float* C;
    if      (OUTSEL == 0) C = g_q;
    else if (OUTSEL == 1) C = g_k;
    else if (OUTSEL == 2) C = g_v;
    else                  C = Cext;

    // [row][k] layout, pad 20 -> conflict-free fragment loads
    __shared__ uint32_t AsHi[128][20];
    __shared__ uint32_t AsLo[128][20];
    __shared__ uint32_t BsHi[128][20];
    __shared__ uint32_t BsLo[128][20];

    const int tid  = threadIdx.x;
    const int warp = tid >> 5, lane = tid & 31;
    const int g    = lane >> 2, tig = lane & 3;
    const int wm   = (warp >> 2) * 64;   // 0 or 64
    const int wn   = (warp & 3) * 32;    // 0..96
    const int blockM = blockIdx.y * 128;
    const int blockN = blockIdx.x * 128;
    const int arow = tid >> 2;           // 0..63
    const int ac4  = tid & 3;            // 0..3

    float acc[4][4][4];
    #pragma unroll
    for (int mt = 0; mt < 4; mt++)
        #pragma unroll
        for (int nt = 0; nt < 4; nt++)
            #pragma unroll
            for (int r = 0; r < 4; r++) acc[mt][nt][r] = 0.f;

    for (int kt = 0; kt < 1024; kt += 16) {
        // cooperative load + tf32 hi/lo split
        #pragma unroll
        for (int half = 0; half < 2; half++) {
            int r = arow + half * 64;
            float4 av = *(const float4*)(A + (size_t)(blockM + r) * 1024 + kt + ac4 * 4);
            float4 bv = *(const float4*)(W + (size_t)(blockN + r) * 1024 + kt + ac4 * 4);
            float af[4] = {av.x, av.y, av.z, av.w};
            float bf[4] = {bv.x, bv.y, bv.z, bv.w};
            uint32_t ahi[4], alo[4], bhi[4], blo[4];
            #pragma unroll
            for (int j = 0; j < 4; j++) {
                ahi[j] = f2tf(af[j]);
                alo[j] = f2tf(af[j] - __uint_as_float(ahi[j]));
                bhi[j] = f2tf(bf[j]);
                blo[j] = f2tf(bf[j] - __uint_as_float(bhi[j]));
            }
            *(uint4*)&AsHi[r][ac4*4] = make_uint4(ahi[0],ahi[1],ahi[2],ahi[3]);
            *(uint4*)&AsLo[r][ac4*4] = make_uint4(alo[0],alo[1],alo[2],alo[3]);
            *(uint4*)&BsHi[r][ac4*4] = make_uint4(bhi[0],bhi[1],bhi[2],bhi[3]);
            *(uint4*)&BsLo[r][ac4*4] = make_uint4(blo[0],blo[1],blo[2],blo[3]);
        }
        __syncthreads();

        #pragma unroll
        for (int ks = 0; ks < 2; ks++) {
            const int k0 = ks * 8;
            uint32_t bh[4][2], bl[4][2];
            #pragma unroll
            for (int nt = 0; nt < 4; nt++) {
                int nb = wn + nt * 8 + g;
                bh[nt][0] = BsHi[nb][k0 + tig];
                bh[nt][1] = BsHi[nb][k0 + tig + 4];
                bl[nt][0] = BsLo[nb][k0 + tig];
                bl[nt][1] = BsLo[nb][k0 + tig + 4];
            }
            #pragma unroll
            for (int mt = 0; mt < 4; mt++) {
                int mb = wm + mt * 16;
                uint32_t ah0 = AsHi[mb + g    ][k0 + tig];
                uint32_t ah1 = AsHi[mb + g + 8][k0 + tig];
                uint32_t ah2 = AsHi[mb + g    ][k0 + tig + 4];
                uint32_t ah3 = AsHi[mb + g + 8][k0 + tig + 4];
                uint32_t al0 = AsLo[mb + g    ][k0 + tig];
                uint32_t al1 = AsLo[mb + g + 8][k0 + tig];
                uint32_t al2 = AsLo[mb + g    ][k0 + tig + 4];
                uint32_t al3 = AsLo[mb + g + 8][k0 + tig + 4];
                #pragma unroll
                for (int nt = 0; nt < 4; nt++) {
                    mma8(acc[mt][nt], ah0, ah1, ah2, ah3, bh[nt][0], bh[nt][1]);
                    mma8(acc[mt][nt], al0, al1, al2, al3, bh[nt][0], bh[nt][1]);
                    mma8(acc[mt][nt], ah0, ah1, ah2, ah3, bl[nt][0], bl[nt][1]);
                }
            }
        }
        __syncthreads();
    }

    // epilogue
    #pragma unroll
    for (int mt = 0; mt < 4; mt++) {
        #pragma unroll
        for (int nt = 0; nt < 4; nt++) {
            int m = blockM + wm + mt * 16 + g;
            int n = blockN + wn + nt * 8 + 2 * tig;
            float2 v0 = make_float2(acc[mt][nt][0], acc[mt][nt][1]);
            float2 v1 = make_float2(acc[mt][nt][2], acc[mt][nt][3]);
            if (OUTSEL < 3) {
                int b = m >> 11, s = m & (SEQ - 1);
                int h = n >> 6,  d = n & (HD - 1);
                float* dst = C + (((size_t)(b * NH + h) * SEQ + s) * HD + d);
                *(float2*)dst = v0;
                float* dst2 = C + (((size_t)(b * NH + h) * SEQ + (s + 8)) * HD + d);
                *(float2*)dst2 = v1;
            } else {
                *(float2*)(C + (size_t)m * HSZ + n)       = v0;
                *(float2*)(C + (size_t)(m + 8) * HSZ + n) = v1;
            }
        }
    }
}

// ---------------------------------------------------------------------------
// Tensor-core flash attention (tf32, single pass).
// Block: 128 query rows, one (b,h). 8 warps x 16 rows. KV tiles of 64.
// Smem (dynamic): Ks[64][68] tf32, Vs[64][68] tf32, Ps[128][68] (Q stage -> P)
// ---------------------------------------------------------------------------
__global__ __launch_bounds__(256)
void attn_tc(const unsigned char* __restrict__ mask)
{
    extern __shared__ uint32_t dsm[];
    uint32_t (*Ks)[68] = (uint32_t(*)[68])dsm;
    uint32_t (*Vs)[68] = (uint32_t(*)[68])(dsm + 64 * 68);
    uint32_t (*Ps)[68] = (uint32_t(*)[68])(dsm + 2 * 64 * 68);
    float    (*Pf)[68] = (float   (*)[68])(dsm + 2 * 64 * 68);

    const int bh = blockIdx.y;
    const int b  = bh >> 4, h = bh & 15;
    const int m0 = blockIdx.x * 128;
    const int tid = threadIdx.x;
    const int warp = tid >> 5, lane = tid & 31;
    const int g = lane >> 2, tig = lane & 3;
    const int mw = warp * 16;

    const float* qbase = g_q + (size_t)bh * SEQ * HD;
    const float* kbase = g_k + (size_t)bh * SEQ * HD;
    const float* vbase = g_v + (size_t)bh * SEQ * HD;

    // stage Q (fp32) into Pf
    for (int i = tid; i < 128 * 16; i += 256) {
        int r = i >> 4, c4 = i & 15;
        *(float4*)&Pf[r][c4 * 4] = *(const float4*)(qbase + (size_t)(m0 + r) * HD + c4 * 4);
    }
    __syncthreads();

    // Q fragments (pre-scaled by 1/sqrt(64)=0.125, tf32), register-resident
    uint32_t qa[8][4];
    #pragma unroll
    for (int kd = 0; kd < 8; kd++) {
        qa[kd][0] = f2tf(0.125f * Pf[mw + g    ][kd * 8 + tig]);
        qa[kd][1] = f2tf(0.125f * Pf[mw + g + 8][kd * 8 + tig]);
        qa[kd][2] = f2tf(0.125f * Pf[mw + g    ][kd * 8 + tig + 4]);
        qa[kd][3] = f2tf(0.125f * Pf[mw + g + 8][kd * 8 + tig + 4]);
    }

    float O[8][4];
    #pragma unroll
    for (int dt = 0; dt < 8; dt++)
        O[dt][0] = O[dt][1] = O[dt][2] = O[dt][3] = 0.f;
    float m_a = -1e30f, m_b = -1e30f, l_a = 0.f, l_b = 0.f;

    for (int n0 = 0; n0 < SEQ; n0 += 64) {
        __syncthreads();   // prior tile's Ks/Vs reads done
        for (int i = tid; i < 64 * 16; i += 256) {
            int r = i >> 4, c4 = i & 15;
            float4 kv = *(const float4*)(kbase + (size_t)(n0 + r) * HD + c4 * 4);
            float4 vv = *(const float4*)(vbase + (size_t)(n0 + r) * HD + c4 * 4);
            *(uint4*)&Ks[r][c4*4] = make_uint4(f2tf(kv.x), f2tf(kv.y), f2tf(kv.z), f2tf(kv.w));
            *(uint4*)&Vs[r][c4*4] = make_uint4(f2tf(vv.x), f2tf(vv.y), f2tf(vv.z), f2tf(vv.w));
        }
        __syncthreads();

        // S = (Q*scale) @ K^T   (16 x 64 per warp)
        float S[8][4];
        #pragma unroll
        for (int nt = 0; nt < 8; nt++) {
            S[nt][0] = S[nt][1] = S[nt][2] = S[nt][3] = 0.f;
            #pragma unroll
            for (int kd = 0; kd < 8; kd++) {
                uint32_t b0 = Ks[nt * 8 + g][kd * 8 + tig];
                uint32_t b1 = Ks[nt * 8 + g][kd * 8 + tig + 4];
                mma8(S[nt], qa[kd][0], qa[kd][1], qa[kd][2], qa[kd][3], b0, b1);
            }
        }

        // mask
        #pragma unroll
        for (int nt = 0; nt < 8; nt++) {
            int n = n0 + nt * 8 + 2 * tig;
            const unsigned char* mrow = mask + ((size_t)b * SEQ + (m0 + mw + g)) * SEQ + n;
            uchar2 ma = *(const uchar2*)mrow;
            uchar2 mb2 = *(const uchar2*)(mrow + (size_t)8 * SEQ);
            if (ma.x)  S[nt][0] = -1e30f;
            if (ma.y)  S[nt][1] = -1e30f;
            if (mb2.x) S[nt][2] = -1e30f;
            if (mb2.y) S[nt][3] = -1e30f;
        }

        // online softmax (rows g and g+8)
        float rmax_a = -1e30f, rmax_b = -1e30f;
        #pragma unroll
        for (int nt = 0; nt < 8; nt++) {
            rmax_a = fmaxf(rmax_a, fmaxf(S[nt][0], S[nt][1]));
            rmax_b = fmaxf(rmax_b, fmaxf(S[nt][2], S[nt][3]));
        }
        rmax_a = fmaxf(rmax_a, __shfl_xor_sync(0xffffffffu, rmax_a, 1));
        rmax_a = fmaxf(rmax_a, __shfl_xor_sync(0xffffffffu, rmax_a, 2));
        rmax_b = fmaxf(rmax_b, __shfl_xor_sync(0xffffffffu, rmax_b, 1));
        rmax_b = fmaxf(rmax_b, __shfl_xor_sync(0xffffffffu, rmax_b, 2));

        float mna = fmaxf(m_a, rmax_a), mnb = fmaxf(m_b, rmax_b);
        float alpha_a = __expf(m_a - mna), alpha_b = __expf(m_b - mnb);
        m_a = mna; m_b = mnb;

        float rs_a = 0.f, rs_b = 0.f;
        #pragma unroll
        for (int nt = 0; nt < 8; nt++) {
            float p0 = __expf(S[nt][0] - mna);
            float p1 = __expf(S[nt][1] - mna);
            float p2 = __expf(S[nt][2] - mnb);
            float p3 = __expf(S[nt][3] - mnb);
            rs_a += p0 + p1; rs_b += p2 + p3;
            Ps[mw + g    ][nt * 8 + 2 * tig]     = f2tf(p0);
            Ps[mw + g    ][nt * 8 + 2 * tig + 1] = f2tf(p1);
            Ps[mw + g + 8][nt * 8 + 2 * tig]     = f2tf(p2);
            Ps[mw + g + 8][nt * 8 + 2 * tig + 1] = f2tf(p3);
        }
        rs_a += __shfl_xor_sync(0xffffffffu, rs_a, 1);
        rs_a += __shfl_xor_sync(0xffffffffu, rs_a, 2);
        rs_b += __shfl_xor_sync(0xffffffffu, rs_b, 1);
        rs_b += __shfl_xor_sync(0xffffffffu, rs_b, 2);
        l_a = l_a * alpha_a + rs_a;
        l_b = l_b * alpha_b + rs_b;
        #pragma unroll
        for (int dt = 0; dt < 8; dt++) {
            O[dt][0] *= alpha_a; O[dt][1] *= alpha_a;
            O[dt][2] *= alpha_b; O[dt][3] *= alpha_b;
        }
        __syncwarp();

        // O += P @ V
        #pragma unroll
        for (int kk = 0; kk < 8; kk++) {
            uint32_t pa0 = Ps[mw + g    ][kk * 8 + tig];
            uint32_t pa1 = Ps[mw + g + 8][kk * 8 + tig];
            uint32_t pa2 = Ps[mw + g    ][kk * 8 + tig + 4];
            uint32_t pa3 = Ps[mw + g + 8][kk * 8 + tig + 4];
            #pragma unroll
            for (int dt = 0; dt < 8; dt++) {
                uint32_t b0 = Vs[kk * 8 + tig    ][dt * 8 + g];
                uint32_t b1 = Vs[kk * 8 + tig + 4][dt * 8 + g];
                mma8(O[dt], pa0, pa1, pa2, pa3, b0, b1);
            }
        }
    }

    // write normalized output, assembled [b,s,hs]
    float inva = 1.0f / l_a, invb = 1.0f / l_b;
    #pragma unroll
    for (int dt = 0; dt < 8; dt++) {
        int d = h * HD + dt * 8 + 2 * tig;
        float* dst0 = g_attn + ((size_t)(b * SEQ + m0 + mw + g)) * HSZ + d;
        *(float2*)dst0 = make_float2(O[dt][0] * inva, O[dt][1] * inva);
        float* dst1 = g_attn + ((size_t)(b * SEQ + m0 + mw + g + 8)) * HSZ + d;
        *(float2*)dst1 = make_float2(O[dt][2] * invb, O[dt][3] * invb);
    }
}

// ---------------------------------------------------------------------------
extern "C" void kernel_launch(void* const* d_in, const int* in_sizes, int n_in,
                              void* d_out, int out_size)
{
    const float* Q  = (const float*)d_in[0];
    const float* K  = (const float*)d_in[1];
    const float* V  = (const float*)d_in[2];
    const unsigned char* mask = (const unsigned char*)d_in[3];
    const float* Wq = (const float*)d_in[4];
    const float* Wk = (const float*)d_in[5];
    const float* Wv = (const float*)d_in[6];
    const float* Wo = (const float*)d_in[7];
    float* out = (float*)d_out;

    dim3 gGemm(HSZ / 128, MTOT / 128);   // (8, 64)

    gemm_tf32<0,0><<<gGemm, 256>>>(Q, Wq, nullptr);
    gemm_tf32<0,1><<<gGemm, 256>>>(K, Wk, nullptr);
    gemm_tf32<0,2><<<gGemm, 256>>>(V, Wv, nullptr);

    const int attnSmem = (2 * 64 * 68 + 128 * 68) * (int)sizeof(uint32_t);  // 69632
    cudaFuncSetAttribute(attn_tc, cudaFuncAttributeMaxDynamicSharedMemorySize, attnSmem);
    attn_tc<<<dim3(SEQ / 128, BSZ * NH), 256, attnSmem>>>(mask);

    gemm_tf32<1,3><<<gGemm, 256>>>(nullptr, Wo, out);
}